// round 15
// baseline (speedup 1.0000x reference)
#include <cuda_runtime.h>
#include <cuda_bf16.h>
#include <cstdint>
#include <math.h>

#define C_IN   1024
#define HH     100
#define WW     100
#define NPIX   (HH*WW)
#define NANCH  90000
#define PRE    6000
#define POST   300
#define NW     188
#define CAND_CAP 16384

#define PQ     102              // padded width/height
#define NQ     (PQ*PQ)          // 10404 padded pixels
#define KP     3072             // expanded k' per tap = 3*1024
#define KC     64               // k' per chunk (128B row)
#define CPT    48               // chunks per tap
#define NCHUNK 432              // 9*48
#define MT     80               // M tiles (128 consecutive padded px each)

// ---------------- static device scratch ----------------
__device__ __align__(128) __nv_bfloat16 g_xa[NQ * KP];          // ~63.9MB
__device__ __align__(128) __nv_bfloat16 g_wb[9 * 1024 * KP];    // ~56.6MB
__device__ float g_y [C_IN * NPIX];
__device__ float g_hp[8 * NPIX * 45];
__device__ unsigned g_hist[65536];
__device__ unsigned g_cnt;
__device__ unsigned g_bthr;
__device__ unsigned long long g_cand[CAND_CAP];
__device__ unsigned long long g_sorted[PRE];
__device__ float g_prop[PRE * 4];
__device__ int   g_valid[PRE];
__device__ unsigned g_supp[PRE * NW];
__device__ unsigned g_keep[NW];

// ---------------- PTX helpers (compute_80-safe only) ----------------
__device__ __forceinline__ uint32_t smem_u32(const void* p) {
    uint32_t a;
    asm("{ .reg .u64 t; cvta.to.shared.u64 t, %1; cvt.u32.u64 %0, t; }" : "=r"(a) : "l"(p));
    return a;
}
#define CP_ASYNC16(d, s) asm volatile("cp.async.cg.shared.global [%0], [%1], 16;" :: "r"(d), "l"(s))
#define CP_COMMIT()      asm volatile("cp.async.commit_group;" ::: "memory")
#define CP_WAIT(n)       asm volatile("cp.async.wait_group %0;" :: "n"(n) : "memory")

__device__ __forceinline__ void ldsm_x4(uint32_t& r0, uint32_t& r1, uint32_t& r2, uint32_t& r3,
                                        uint32_t addr) {
    asm volatile("ldmatrix.sync.aligned.m8n8.x4.shared.b16 {%0,%1,%2,%3}, [%4];"
                 : "=r"(r0), "=r"(r1), "=r"(r2), "=r"(r3) : "r"(addr));
}
__device__ __forceinline__ void mma16816(float* c, const uint32_t* a, uint32_t b0, uint32_t b1) {
    asm volatile("mma.sync.aligned.m16n8k16.row.col.f32.bf16.bf16.f32 "
                 "{%0,%1,%2,%3}, {%4,%5,%6,%7}, {%8,%9}, {%0,%1,%2,%3};"
                 : "+f"(c[0]), "+f"(c[1]), "+f"(c[2]), "+f"(c[3])
                 : "r"(a[0]), "r"(a[1]), "r"(a[2]), "r"(a[3]), "r"(b0), "r"(b1));
}

__device__ __forceinline__ unsigned f2sortable(float s) {
    unsigned u = __float_as_uint(s);
    return (u & 0x80000000u) ? ~u : (u | 0x80000000u);
}

// ---------------- 1a. zero-fill border pixels of g_xa ----------------
__global__ void pad_fill() {
    int b = blockIdx.x;   // 0..403
    int q;
    if (b < 102)       q = b;                       // row 0
    else if (b < 204)  q = 101 * PQ + (b - 102);    // row 101
    else if (b < 304)  q = (b - 204 + 1) * PQ;      // col 0, rows 1..100
    else               q = (b - 304 + 1) * PQ + 101;// col 101
    uint4 z = make_uint4(0, 0, 0, 0);
    uint4* dst = (uint4*)((char*)g_xa + (long long)q * KP * 2);
    for (int i = threadIdx.x; i < (KP * 2) / 16; i += blockDim.x) dst[i] = z;
}

// ---------------- 1b. expand activations (coalesced both sides via smem transpose) ----------------
__global__ void expand_x(const float* __restrict__ x) {
    __shared__ float s[32][33];
    const int tx = threadIdx.x, ty = threadIdx.y;   // block (32,8)
    const int pix0 = blockIdx.x * 32, ci0 = blockIdx.y * 32;
#pragma unroll
    for (int i = 0; i < 4; ++i) {
        int ci = ty + 8 * i;
        int p  = pix0 + tx;
        s[ci][tx] = (p < NPIX) ? x[(ci0 + ci) * NPIX + p] : 0.f;
    }
    __syncthreads();
#pragma unroll
    for (int i = 0; i < 4; ++i) {
        int p = pix0 + ty + 8 * i;
        if (p < NPIX) {
            float v = s[tx][ty + 8 * i];
            __nv_bfloat16 a0 = __float2bfloat16(v);
            __nv_bfloat16 a1 = __float2bfloat16(v - __bfloat162float(a0));
            int q = (p / WW + 1) * PQ + (p % WW + 1);
            __nv_bfloat16* dst = g_xa + (long long)q * KP + 3 * (ci0 + tx);
            dst[0] = a0; dst[1] = a0; dst[2] = a1;
        }
    }
}

// ---------------- 2. expand weights (one CTA per co, coalesced) ----------------
__global__ void expand_w(const float* __restrict__ w1) {
    __shared__ float ws[9216];
    const int co = blockIdx.x, tid = threadIdx.x;
    const float* src = w1 + (long long)co * 9216;
    for (int e = tid; e < 9216; e += 256) ws[e] = src[e];
    __syncthreads();
#pragma unroll 1
    for (int tap = 0; tap < 9; ++tap) {
        __nv_bfloat16* drow = g_wb + (long long)(tap * 1024 + co) * KP;
        for (int ci = tid; ci < 1024; ci += 256) {
            float v = ws[ci * 9 + tap];
            __nv_bfloat16 b0 = __float2bfloat16(v);
            __nv_bfloat16 b1 = __float2bfloat16(v - __bfloat162float(b0));
            __nv_bfloat16* dst = drow + 3 * ci;
            dst[0] = b0; dst[1] = b1; dst[2] = b0;
        }
    }
}

// ---------------- 3. conv via mma.sync implicit GEMM, linear-q tiles ----------------
// grid(80 qtiles, 4 co-tiles of 256), 512 threads (16 warps 2Mx8N, warp=M64xN32),
// 144KB dyn smem, 3-stage cp.async pipeline
#define ASZ 16384     // 128 rows * 128B
#define BSZ 32768     // 256 rows * 128B
__global__ __launch_bounds__(512, 1) void conv_mma(const float* __restrict__ b1) {
    extern __shared__ char dsm[];
    const int tid = threadIdx.x, wid = tid >> 5, lane = tid & 31;
    const int wm = wid & 1, wn = wid >> 1;       // wm: 2 M-groups, wn: 8 N-groups
    const int q0 = 103 + blockIdx.x * 128, co0 = blockIdx.y * 256;
    const uint32_t As = smem_u32(dsm);
    const uint32_t Bs = As + 3 * ASZ;

    float acc[4][4][4];                          // f(16-row) x 4 n8-blocks x 4
#pragma unroll
    for (int f = 0; f < 4; ++f)
#pragma unroll
        for (int g = 0; g < 4; ++g)
#pragma unroll
            for (int q = 0; q < 4; ++q) acc[f][g][q] = 0.f;

    auto load_chunk = [&](int c, int buf) {
        const int tap = c / CPT;
        const int ko  = (c - tap * CPT) * KC;
        const int dh = tap / 3, dw = tap - 3 * dh;
        const int off = (dh - 1) * PQ + (dw - 1);
        const char* bsrc = (const char*)g_wb +
            ((long long)(tap * 1024 + co0) * KP + ko) * 2;
        const uint32_t ab = As + buf * ASZ;
        const uint32_t bb = Bs + buf * BSZ;
#pragma unroll
        for (int i = 0; i < 2; ++i) {            // A: 128 rows x 8 x 16B = 1024
            int o = tid + 512 * i;
            int row = o >> 3, seg = o & 7;
            int qs = q0 + row + off;
            qs = qs < 0 ? 0 : (qs > NQ - 1 ? NQ - 1 : qs);
            CP_ASYNC16(ab + row * 128 + ((seg ^ (row & 7)) << 4),
                       (const char*)g_xa + ((long long)qs * KP + ko) * 2 + seg * 16);
        }
#pragma unroll
        for (int i = 0; i < 4; ++i) {            // B: 256 rows x 8 x 16B = 2048
            int o = tid + 512 * i;
            int row = o >> 3, seg = o & 7;
            CP_ASYNC16(bb + row * 128 + ((seg ^ (row & 7)) << 4),
                       bsrc + (long long)row * (KP * 2) + seg * 16);
        }
        CP_COMMIT();
    };

    load_chunk(0, 0);
    load_chunk(1, 1);
    int buf = 0, nbuf = 2;
    for (int c = 0; c < NCHUNK; ++c) {
        if (c + 2 < NCHUNK) { load_chunk(c + 2, nbuf); CP_WAIT(2); }
        else if (c + 1 < NCHUNK) { CP_WAIT(1); }
        else { CP_WAIT(0); }
        __syncthreads();
        const uint32_t ab = As + buf * ASZ;
        const uint32_t bb = Bs + buf * BSZ;
#pragma unroll
        for (int s = 0; s < 4; ++s) {
            uint32_t a[4][4], b[2][4];
#pragma unroll
            for (int f = 0; f < 4; ++f) {
                int row = wm * 64 + f * 16 + (lane & 15);
                int seg = 2 * s + (lane >> 4);
                ldsm_x4(a[f][0], a[f][1], a[f][2], a[f][3],
                        ab + row * 128 + ((seg ^ (row & 7)) << 4));
            }
#pragma unroll
            for (int g = 0; g < 2; ++g) {
                int row = wn * 32 + g * 16 + (lane & 7) + ((lane >> 4) << 3);
                int seg = 2 * s + ((lane >> 3) & 1);
                ldsm_x4(b[g][0], b[g][1], b[g][2], b[g][3],
                        bb + row * 128 + ((seg ^ (row & 7)) << 4));
            }
#pragma unroll
            for (int f = 0; f < 4; ++f)
#pragma unroll
                for (int g = 0; g < 2; ++g) {
                    mma16816(acc[f][2 * g],     a[f], b[g][0], b[g][1]);
                    mma16816(acc[f][2 * g + 1], a[f], b[g][2], b[g][3]);
                }
        }
        __syncthreads();
        buf = buf + 1 == 3 ? 0 : buf + 1;
        nbuf = nbuf + 1 == 3 ? 0 : nbuf + 1;
    }

    // epilogue: bias + relu -> g_y[co][pix]
#pragma unroll
    for (int f = 0; f < 4; ++f) {
        int row0 = wm * 64 + f * 16 + (lane >> 2);
        int row1 = row0 + 8;
        int qa = q0 + row0, qb = q0 + row1;
        int r0 = qa / PQ - 1, c0c = qa % PQ - 1;
        int r1 = qb / PQ - 1, c1c = qb % PQ - 1;
        bool v0 = (unsigned)r0 < HH && (unsigned)c0c < WW;
        bool v1 = (unsigned)r1 < HH && (unsigned)c1c < WW;
        int p0 = r0 * WW + c0c, p1 = r1 * WW + c1c;
#pragma unroll
        for (int g = 0; g < 4; ++g) {
            int co = co0 + wn * 32 + g * 8 + 2 * (lane & 3);
            float bia = b1[co], bib = b1[co + 1];
            if (v0) {
                float va = acc[f][g][0] + bia;
                float vb = acc[f][g][1] + bib;
                g_y[co * NPIX + p0]       = va > 0.f ? va : 0.f;
                g_y[(co + 1) * NPIX + p0] = vb > 0.f ? vb : 0.f;
            }
            if (v1) {
                float vc = acc[f][g][2] + bia;
                float vd = acc[f][g][3] + bib;
                g_y[co * NPIX + p1]       = vc > 0.f ? vc : 0.f;
                g_y[(co + 1) * NPIX + p1] = vd > 0.f ? vd : 0.f;
            }
        }
    }
}

// ---------------- 4a. heads split-K partials ----------------
__global__ __launch_bounds__(128) void heads_part(const float* __restrict__ wcls,
                                                  const float* __restrict__ wbox) {
    __shared__ float wsm[128][45];
    const int tid = threadIdx.x;
    const int px  = blockIdx.x * 128 + tid;
    const int pxl = px < NPIX ? px : (NPIX - 1);
    const int ci0 = blockIdx.y * 128;

    for (int e = tid; e < 128 * 45; e += 128) {
        int ci_ = e / 45, o = e - ci_ * 45;
        wsm[ci_][o] = (o < 9) ? wcls[o * C_IN + ci0 + ci_]
                              : wbox[(o - 9) * C_IN + ci0 + ci_];
    }
    __syncthreads();

    float acc[45];
#pragma unroll
    for (int o = 0; o < 45; ++o) acc[o] = 0.f;
    for (int ci_ = 0; ci_ < 128; ++ci_) {
        float yv = g_y[(ci0 + ci_) * NPIX + pxl];
#pragma unroll
        for (int o = 0; o < 45; ++o) acc[o] = fmaf(yv, wsm[ci_][o], acc[o]);
    }
    if (px < NPIX) {
        float* dst = g_hp + ((long long)blockIdx.y * NPIX + px) * 45;
#pragma unroll
        for (int o = 0; o < 45; ++o) dst[o] = acc[o];
    }
}

// ---------------- 4b. heads reduce + bias + sigmoid ----------------
__global__ void heads_reduce(const float* __restrict__ bcls,
                             const float* __restrict__ bbox,
                             float* __restrict__ out) {
    int t = blockIdx.x * blockDim.x + threadIdx.x;
    if (t >= NPIX * 45) return;
    int px = t / 45, o = t - px * 45;
    float s = 0.f;
#pragma unroll
    for (int p = 0; p < 8; ++p) s += g_hp[((long long)p * NPIX + px) * 45 + o];
    if (o < 9) {
        float logit = s + bcls[o];
        out[px * 9 + o] = 1.f / (1.f + expf(-logit));
    } else {
        out[NANCH + px * 36 + (o - 9)] = s + bbox[o - 9];
    }
}

// ---------------- 5. top-k selection ----------------
__global__ void clear_kernel() {
    int t = blockIdx.x * blockDim.x + threadIdx.x;
    if (t < 65536) g_hist[t] = 0;
    if (t == 0) g_cnt = 0;
}
__global__ void hist_kernel(const float* __restrict__ out) {
    int t = blockIdx.x * blockDim.x + threadIdx.x;
    if (t >= NANCH) return;
    unsigned u = f2sortable(out[t]);
    atomicAdd(&g_hist[u >> 16], 1u);
}
__global__ void thresh_kernel() {
    __shared__ unsigned suf[257];
    int t = threadIdx.x;
    unsigned s = 0;
    for (int b = 0; b < 256; ++b) s += g_hist[t * 256 + b];
    suf[t] = s;
    __syncthreads();
    if (t == 0) {
        unsigned acc = 0;
        for (int q = 255; q >= 0; --q) { unsigned v = suf[q]; suf[q] = acc; acc += v; }
        suf[256] = acc;
    }
    __syncthreads();
    unsigned after = suf[t];
    if (after < PRE && after + s >= PRE) {
        unsigned acc = after;
        int bthr = t * 256;
        for (int b = t * 256 + 255; b >= t * 256; --b) {
            acc += g_hist[b];
            if (acc >= PRE) { bthr = b; break; }
        }
        g_bthr = (unsigned)bthr;
    }
}
__global__ void compact_kernel(const float* __restrict__ out) {
    int t = blockIdx.x * blockDim.x + threadIdx.x;
    if (t >= NANCH) return;
    unsigned u = f2sortable(out[t]);
    if ((u >> 16) >= g_bthr) {
        unsigned p = atomicAdd(&g_cnt, 1u);
        if (p < CAND_CAP)
            g_cand[p] = ((unsigned long long)u << 32) | (unsigned)t;
    }
}
__global__ void sort_kernel() {
    extern __shared__ unsigned long long sk[];
    const int tid = threadIdx.x;
    int nc = g_cnt; if (nc > CAND_CAP) nc = CAND_CAP;
    for (int i = tid; i < CAND_CAP; i += blockDim.x)
        sk[i] = (i < nc) ? g_cand[i] : 0ull;
    __syncthreads();
    for (int k = 2; k <= CAND_CAP; k <<= 1) {
        for (int j = k >> 1; j > 0; j >>= 1) {
            for (int i = tid; i < CAND_CAP; i += blockDim.x) {
                int ixj = i ^ j;
                if (ixj > i) {
                    unsigned long long a = sk[i], b = sk[ixj];
                    bool sw = ((i & k) == 0) ? (a < b) : (a > b);
                    if (sw) { sk[i] = b; sk[ixj] = a; }
                }
            }
            __syncthreads();
        }
    }
    for (int i = tid; i < PRE; i += blockDim.x) g_sorted[i] = sk[i];
}

// ---------------- 6. decode proposals ----------------
__global__ void decode_kernel(const float* __restrict__ am,
                              const int* __restrict__ ish,
                              const float* __restrict__ out) {
    int i = blockIdx.x * blockDim.x + threadIdx.x;
    if (i >= PRE) return;
    unsigned idx = (unsigned)(g_sorted[i] & 0xFFFFFFFFull);
    float a0 = am[idx * 4 + 0], a1 = am[idx * 4 + 1];
    float a2 = am[idx * 4 + 2], a3 = am[idx * 4 + 3];
    const float* d = out + NANCH + idx * 4;
    float cy = a0 + d[0] * a2;
    float cx = a1 + d[1] * a3;
    float sh = a2 * expf(d[2]);
    float sw = a3 * expf(d[3]);
    float y1 = cy - 0.5f * sh, x1 = cx - 0.5f * sw;
    float y2 = cy + 0.5f * sh, x2 = cx + 0.5f * sw;
    y1 = fmaxf(y1, 0.f); x1 = fmaxf(x1, 0.f);
    y2 = fminf(y2, (float)ish[1]);
    x2 = fminf(x2, (float)ish[2]);
    g_prop[i * 4 + 0] = y1; g_prop[i * 4 + 1] = x1;
    g_prop[i * 4 + 2] = y2; g_prop[i * 4 + 3] = x2;
    g_valid[i] = ((y2 - y1) >= 16.f) && ((x2 - x1) >= 16.f);
}

// ---------------- 7. NMS suppression bitmatrix ----------------
__global__ void nmsmat_kernel() {
    int t = blockIdx.x * blockDim.x + threadIdx.x;
    if (t >= PRE * NW) return;
    int i = t / NW;
    int w = t - i * NW;
    float y1 = g_prop[i * 4 + 0], x1 = g_prop[i * 4 + 1];
    float y2 = g_prop[i * 4 + 2], x2 = g_prop[i * 4 + 3];
    float ai = (y2 - y1) * (x2 - x1);
    unsigned bits = 0;
    int j0 = w * 32;
#pragma unroll 4
    for (int b = 0; b < 32; ++b) {
        int j = j0 + b;
        if (j < PRE && j > i) {
            float jy1 = g_prop[j * 4 + 0], jx1 = g_prop[j * 4 + 1];
            float jy2 = g_prop[j * 4 + 2], jx2 = g_prop[j * 4 + 3];
            float aj = (jy2 - jy1) * (jx2 - jx1);
            float iy1 = fmaxf(y1, jy1), ix1 = fmaxf(x1, jx1);
            float iy2 = fminf(y2, jy2), ix2 = fminf(x2, jx2);
            float inter = fmaxf(iy2 - iy1, 0.f) * fmaxf(ix2 - ix1, 0.f);
            float iou = inter / (ai + aj - inter + 1e-8f);
            if (iou > 0.7f) bits |= (1u << b);
        }
    }
    g_supp[t] = bits;
}

// ---------------- 8. sequential NMS scan (D-prefetch pipeline, proven R5) ----------------
__global__ void nmsscan_kernel() {
    __shared__ unsigned km[NW];
    const int t = threadIdx.x;  // 192
    if (t < NW) {
        unsigned bits = 0;
        for (int b = 0; b < 32; ++b) {
            int i = t * 32 + b;
            if (i < PRE && g_valid[i]) bits |= (1u << b);
        }
        km[t] = bits;
    }
    __syncthreads();
    const int D = 6;
    unsigned pre[D];
#pragma unroll
    for (int d = 0; d < D; ++d)
        pre[d] = (t < NW && d < PRE) ? g_supp[d * NW + t] : 0u;
    for (int i = 0; i < PRE; ++i) {
        unsigned row = pre[0];
#pragma unroll
        for (int d = 0; d < D - 1; ++d) pre[d] = pre[d + 1];
        int nx = i + D;
        pre[D - 1] = (t < NW && nx < PRE) ? g_supp[nx * NW + t] : 0u;
        bool kept = (km[i >> 5] >> (i & 31)) & 1u;
        if (kept && t < NW) km[t] &= ~row;
        __syncthreads();
    }
    if (t < NW) g_keep[t] = km[t];
}

// ---------------- 9. gather top-300 kept ----------------
__global__ void gather_kernel(float* __restrict__ out) {
    __shared__ unsigned pref[NW + 1];
    __shared__ unsigned kmw[NW];
    const int t = threadIdx.x;  // 256
    for (int w = t; w < NW; w += blockDim.x) kmw[w] = g_keep[w];
    __syncthreads();
    if (t == 0) {
        unsigned acc = 0;
        for (int w = 0; w < NW; ++w) { pref[w] = acc; acc += __popc(kmw[w]); }
        pref[NW] = acc;
    }
    __syncthreads();
    unsigned total = pref[NW];
    for (int i = t; i < PRE; i += blockDim.x) {
        unsigned word = kmw[i >> 5];
        if ((word >> (i & 31)) & 1u) {
            unsigned r = pref[i >> 5] + __popc(word & ((1u << (i & 31)) - 1u));
            if (r < POST) {
                out[NANCH * 5 + r * 4 + 0] = g_prop[i * 4 + 0];
                out[NANCH * 5 + r * 4 + 1] = g_prop[i * 4 + 1];
                out[NANCH * 5 + r * 4 + 2] = g_prop[i * 4 + 2];
                out[NANCH * 5 + r * 4 + 3] = g_prop[i * 4 + 3];
            }
        }
    }
    for (int k = t; k < POST; k += blockDim.x) {
        if ((unsigned)k >= total) {
            out[NANCH * 5 + k * 4 + 0] = 0.f;
            out[NANCH * 5 + k * 4 + 1] = 0.f;
            out[NANCH * 5 + k * 4 + 2] = 0.f;
            out[NANCH * 5 + k * 4 + 3] = 0.f;
        }
    }
}

// ---------------- launch ----------------
extern "C" void kernel_launch(void* const* d_in, const int* in_sizes, int n_in,
                              void* d_out, int out_size) {
    const float *feat = nullptr, *am = nullptr, *w1 = nullptr, *b1 = nullptr;
    const float *wcls = nullptr, *bcls = nullptr, *wbox = nullptr, *bbox = nullptr;
    const int *ish = nullptr;
    for (int i = 0; i < n_in; ++i) {
        switch (in_sizes[i]) {
            case 10240000: feat = (const float*)d_in[i]; break;
            case 3:        ish  = (const int*)d_in[i]; break;
            case 360000:   am   = (const float*)d_in[i]; break;
            case 9437184:  w1   = (const float*)d_in[i]; break;
            case 1024:     b1   = (const float*)d_in[i]; break;
            case 9216:     wcls = (const float*)d_in[i]; break;
            case 9:        bcls = (const float*)d_in[i]; break;
            case 36864:    wbox = (const float*)d_in[i]; break;
            case 36:       bbox = (const float*)d_in[i]; break;
            default: break;
        }
    }
    float* out = (float*)d_out;

    const int CONV_SMEM = 3 * (ASZ + BSZ);   // 147456
    cudaFuncSetAttribute(conv_mma, cudaFuncAttributeMaxDynamicSharedMemorySize, CONV_SMEM);
    cudaFuncSetAttribute(sort_kernel, cudaFuncAttributeMaxDynamicSharedMemorySize,
                         CAND_CAP * (int)sizeof(unsigned long long));

    pad_fill<<<404, 256>>>();
    {
        dim3 grid((NPIX + 31) / 32, C_IN / 32);
        dim3 blk(32, 8);
        expand_x<<<grid, blk>>>(feat);
    }
    expand_w<<<1024, 256>>>(w1);
    {
        dim3 grid(MT, 4);
        conv_mma<<<grid, 512, CONV_SMEM>>>(b1);
    }
    {
        dim3 grid((NPIX + 127) / 128, 8);
        heads_part<<<grid, 128>>>(wcls, wbox);
    }
    heads_reduce<<<(NPIX * 45 + 255) / 256, 256>>>(bcls, bbox, out);
    clear_kernel<<<65536 / 256, 256>>>();
    hist_kernel<<<(NANCH + 255) / 256, 256>>>(out);
    thresh_kernel<<<1, 256>>>();
    compact_kernel<<<(NANCH + 255) / 256, 256>>>(out);
    sort_kernel<<<1, 1024, CAND_CAP * sizeof(unsigned long long)>>>();
    decode_kernel<<<(PRE + 255) / 256, 256>>>(am, ish, out);
    nmsmat_kernel<<<(PRE * NW + 255) / 256, 256>>>();
    nmsscan_kernel<<<1, 192>>>();
    gather_kernel<<<1, 256>>>(out);
}

// round 17
// speedup vs baseline: 1.1767x; 1.1767x over previous
#include <cuda_runtime.h>
#include <cuda_bf16.h>
#include <cstdint>
#include <math.h>

#define C_IN   1024
#define HH     100
#define WW     100
#define NPIX   (HH*WW)
#define NANCH  90000
#define PRE    6000
#define POST   300
#define NW     188
#define CAND_CAP 16384

#define PQ     102              // padded width/height
#define NQ     (PQ*PQ)          // 10404 padded pixels
#define KP     3072             // expanded k' per tap = 3*1024
#define KC     64               // k' per chunk (128B row)
#define CPT    48               // chunks per tap
#define NCHUNK 432              // 9*48
#define MTILE  144              // M rows per CTA tile
#define MT     71               // ceil((10300-103+1)/144) -> 71 tiles, 71*4=284 CTAs = 2 waves

// ---------------- static device scratch ----------------
__device__ __align__(128) __nv_bfloat16 g_xa[NQ * KP];          // ~63.9MB
__device__ __align__(128) __nv_bfloat16 g_wb[9 * 1024 * KP];    // ~56.6MB
__device__ float g_y [C_IN * NPIX];
__device__ float g_hp[8 * NPIX * 45];
__device__ unsigned g_hist[65536];
__device__ unsigned g_cnt;
__device__ unsigned g_bthr;
__device__ unsigned long long g_cand[CAND_CAP];
__device__ unsigned long long g_sorted[PRE];
__device__ float g_prop[PRE * 4];
__device__ int   g_valid[PRE];
__device__ unsigned g_supp[PRE * NW];
__device__ unsigned g_keep[NW];

// ---------------- PTX helpers (compute_80-safe only) ----------------
__device__ __forceinline__ uint32_t smem_u32(const void* p) {
    uint32_t a;
    asm("{ .reg .u64 t; cvta.to.shared.u64 t, %1; cvt.u32.u64 %0, t; }" : "=r"(a) : "l"(p));
    return a;
}
#define CP_ASYNC16(d, s) asm volatile("cp.async.cg.shared.global [%0], [%1], 16;" :: "r"(d), "l"(s))
#define CP_COMMIT()      asm volatile("cp.async.commit_group;" ::: "memory")
#define CP_WAIT(n)       asm volatile("cp.async.wait_group %0;" :: "n"(n) : "memory")

__device__ __forceinline__ void ldsm_x4(uint32_t& r0, uint32_t& r1, uint32_t& r2, uint32_t& r3,
                                        uint32_t addr) {
    asm volatile("ldmatrix.sync.aligned.m8n8.x4.shared.b16 {%0,%1,%2,%3}, [%4];"
                 : "=r"(r0), "=r"(r1), "=r"(r2), "=r"(r3) : "r"(addr));
}
__device__ __forceinline__ void mma16816(float* c, const uint32_t* a, uint32_t b0, uint32_t b1) {
    asm volatile("mma.sync.aligned.m16n8k16.row.col.f32.bf16.bf16.f32 "
                 "{%0,%1,%2,%3}, {%4,%5,%6,%7}, {%8,%9}, {%0,%1,%2,%3};"
                 : "+f"(c[0]), "+f"(c[1]), "+f"(c[2]), "+f"(c[3])
                 : "r"(a[0]), "r"(a[1]), "r"(a[2]), "r"(a[3]), "r"(b0), "r"(b1));
}

__device__ __forceinline__ unsigned f2sortable(float s) {
    unsigned u = __float_as_uint(s);
    return (u & 0x80000000u) ? ~u : (u | 0x80000000u);
}

// ---------------- 1a. zero-fill border pixels of g_xa ----------------
__global__ void pad_fill() {
    int b = blockIdx.x;   // 0..403
    int q;
    if (b < 102)       q = b;                       // row 0
    else if (b < 204)  q = 101 * PQ + (b - 102);    // row 101
    else if (b < 304)  q = (b - 204 + 1) * PQ;      // col 0, rows 1..100
    else               q = (b - 304 + 1) * PQ + 101;// col 101
    uint4 z = make_uint4(0, 0, 0, 0);
    uint4* dst = (uint4*)((char*)g_xa + (long long)q * KP * 2);
    for (int i = threadIdx.x; i < (KP * 2) / 16; i += blockDim.x) dst[i] = z;
}

// ---------------- 1b. expand activations (coalesced both sides via smem transpose) ----------------
__global__ void expand_x(const float* __restrict__ x) {
    __shared__ float s[32][33];
    const int tx = threadIdx.x, ty = threadIdx.y;   // block (32,8)
    const int pix0 = blockIdx.x * 32, ci0 = blockIdx.y * 32;
#pragma unroll
    for (int i = 0; i < 4; ++i) {
        int ci = ty + 8 * i;
        int p  = pix0 + tx;
        s[ci][tx] = (p < NPIX) ? x[(ci0 + ci) * NPIX + p] : 0.f;
    }
    __syncthreads();
#pragma unroll
    for (int i = 0; i < 4; ++i) {
        int p = pix0 + ty + 8 * i;
        if (p < NPIX) {
            float v = s[tx][ty + 8 * i];
            __nv_bfloat16 a0 = __float2bfloat16(v);
            __nv_bfloat16 a1 = __float2bfloat16(v - __bfloat162float(a0));
            int q = (p / WW + 1) * PQ + (p % WW + 1);
            __nv_bfloat16* dst = g_xa + (long long)q * KP + 3 * (ci0 + tx);
            dst[0] = a0; dst[1] = a0; dst[2] = a1;
        }
    }
}

// ---------------- 2. expand weights (one CTA per co, coalesced) ----------------
__global__ void expand_w(const float* __restrict__ w1) {
    __shared__ float ws[9216];
    const int co = blockIdx.x, tid = threadIdx.x;
    const float* src = w1 + (long long)co * 9216;
    for (int e = tid; e < 9216; e += 256) ws[e] = src[e];
    __syncthreads();
#pragma unroll 1
    for (int tap = 0; tap < 9; ++tap) {
        __nv_bfloat16* drow = g_wb + (long long)(tap * 1024 + co) * KP;
        for (int ci = tid; ci < 1024; ci += 256) {
            float v = ws[ci * 9 + tap];
            __nv_bfloat16 b0 = __float2bfloat16(v);
            __nv_bfloat16 b1 = __float2bfloat16(v - __bfloat162float(b0));
            __nv_bfloat16* dst = drow + 3 * ci;
            dst[0] = b0; dst[1] = b1; dst[2] = b0;
        }
    }
}

// ---------------- 3. conv via mma.sync implicit GEMM, 2 balanced waves ----------------
// grid(71 qtiles of 144, 4 co-tiles of 256), 384 threads (12 warps 3Mx4N, warp=M48xN64),
// 150KB dyn smem, 3-stage cp.async pipeline
#define ASZ (MTILE * 128)   // 18432
#define BSZ 32768           // 256 rows * 128B
__global__ __launch_bounds__(384, 1) void conv_mma(const float* __restrict__ b1) {
    extern __shared__ char dsm[];
    const int tid = threadIdx.x, wid = tid >> 5, lane = tid & 31;
    const int wm = wid >> 2, wn = wid & 3;       // 3 M-groups x 4 N-groups
    const int q0 = 103 + blockIdx.x * MTILE, co0 = blockIdx.y * 256;
    const uint32_t As = smem_u32(dsm);
    const uint32_t Bs = As + 3 * ASZ;

    float acc[3][8][4];                          // 3 f(16-row) x 8 n8-blocks x 4 = 96 regs
#pragma unroll
    for (int f = 0; f < 3; ++f)
#pragma unroll
        for (int g = 0; g < 8; ++g)
#pragma unroll
            for (int q = 0; q < 4; ++q) acc[f][g][q] = 0.f;

    auto load_chunk = [&](int c, int buf) {
        const int tap = c / CPT;
        const int ko  = (c - tap * CPT) * KC;
        const int dh = tap / 3, dw = tap - 3 * dh;
        const int off = (dh - 1) * PQ + (dw - 1);
        const char* bsrc = (const char*)g_wb +
            ((long long)(tap * 1024 + co0) * KP + ko) * 2;
        const uint32_t ab = As + buf * ASZ;
        const uint32_t bb = Bs + buf * BSZ;
#pragma unroll
        for (int i = 0; i < 3; ++i) {            // A: 144 rows x 8 x 16B = 1152 = 3*384
            int o = tid + 384 * i;
            int row = o >> 3, seg = o & 7;
            int qs = q0 + row + off;
            qs = qs < 0 ? 0 : (qs > NQ - 1 ? NQ - 1 : qs);
            CP_ASYNC16(ab + row * 128 + ((seg ^ (row & 7)) << 4),
                       (const char*)g_xa + ((long long)qs * KP + ko) * 2 + seg * 16);
        }
#pragma unroll
        for (int i = 0; i < 6; ++i) {            // B: 256 rows x 8 x 16B = 2048 (guard 2304)
            int o = tid + 384 * i;
            if (o < 2048) {
                int row = o >> 3, seg = o & 7;
                CP_ASYNC16(bb + row * 128 + ((seg ^ (row & 7)) << 4),
                           bsrc + (long long)row * (KP * 2) + seg * 16);
            }
        }
        CP_COMMIT();
    };

    load_chunk(0, 0);
    load_chunk(1, 1);
    int buf = 0, nbuf = 2;
    for (int c = 0; c < NCHUNK; ++c) {
        if (c + 2 < NCHUNK) { load_chunk(c + 2, nbuf); CP_WAIT(2); }
        else if (c + 1 < NCHUNK) { CP_WAIT(1); }
        else { CP_WAIT(0); }
        __syncthreads();
        const uint32_t ab = As + buf * ASZ;
        const uint32_t bb = Bs + buf * BSZ;
#pragma unroll
        for (int s = 0; s < 4; ++s) {
            uint32_t a[3][4], b[4][4];
#pragma unroll
            for (int f = 0; f < 3; ++f) {
                int row = wm * 48 + f * 16 + (lane & 15);
                int seg = 2 * s + (lane >> 4);
                ldsm_x4(a[f][0], a[f][1], a[f][2], a[f][3],
                        ab + row * 128 + ((seg ^ (row & 7)) << 4));
            }
#pragma unroll
            for (int g = 0; g < 4; ++g) {
                int row = wn * 64 + g * 16 + (lane & 7) + ((lane >> 4) << 3);
                int seg = 2 * s + ((lane >> 3) & 1);
                ldsm_x4(b[g][0], b[g][1], b[g][2], b[g][3],
                        bb + row * 128 + ((seg ^ (row & 7)) << 4));
            }
#pragma unroll
            for (int f = 0; f < 3; ++f)
#pragma unroll
                for (int g = 0; g < 4; ++g) {
                    mma16816(acc[f][2 * g],     a[f], b[g][0], b[g][1]);
                    mma16816(acc[f][2 * g + 1], a[f], b[g][2], b[g][3]);
                }
        }
        __syncthreads();
        buf = buf + 1 == 3 ? 0 : buf + 1;
        nbuf = nbuf + 1 == 3 ? 0 : nbuf + 1;
    }

    // epilogue: bias + relu -> g_y[co][pix]
#pragma unroll
    for (int f = 0; f < 3; ++f) {
        int row0 = wm * 48 + f * 16 + (lane >> 2);
        int row1 = row0 + 8;
        int qa = q0 + row0, qb = q0 + row1;
        int r0 = qa / PQ - 1, c0c = qa % PQ - 1;
        int r1 = qb / PQ - 1, c1c = qb % PQ - 1;
        bool v0 = (unsigned)r0 < HH && (unsigned)c0c < WW;
        bool v1 = (unsigned)r1 < HH && (unsigned)c1c < WW;
        int p0 = r0 * WW + c0c, p1 = r1 * WW + c1c;
#pragma unroll
        for (int g = 0; g < 8; ++g) {
            int co = co0 + wn * 64 + g * 8 + 2 * (lane & 3);
            float bia = b1[co], bib = b1[co + 1];
            if (v0) {
                float va = acc[f][g][0] + bia;
                float vb = acc[f][g][1] + bib;
                g_y[co * NPIX + p0]       = va > 0.f ? va : 0.f;
                g_y[(co + 1) * NPIX + p0] = vb > 0.f ? vb : 0.f;
            }
            if (v1) {
                float vc = acc[f][g][2] + bia;
                float vd = acc[f][g][3] + bib;
                g_y[co * NPIX + p1]       = vc > 0.f ? vc : 0.f;
                g_y[(co + 1) * NPIX + p1] = vd > 0.f ? vd : 0.f;
            }
        }
    }
}

// ---------------- 4a. heads split-K partials ----------------
__global__ __launch_bounds__(128) void heads_part(const float* __restrict__ wcls,
                                                  const float* __restrict__ wbox) {
    __shared__ float wsm[128][45];
    const int tid = threadIdx.x;
    const int px  = blockIdx.x * 128 + tid;
    const int pxl = px < NPIX ? px : (NPIX - 1);
    const int ci0 = blockIdx.y * 128;

    for (int e = tid; e < 128 * 45; e += 128) {
        int ci_ = e / 45, o = e - ci_ * 45;
        wsm[ci_][o] = (o < 9) ? wcls[o * C_IN + ci0 + ci_]
                              : wbox[(o - 9) * C_IN + ci0 + ci_];
    }
    __syncthreads();

    float acc[45];
#pragma unroll
    for (int o = 0; o < 45; ++o) acc[o] = 0.f;
    for (int ci_ = 0; ci_ < 128; ++ci_) {
        float yv = g_y[(ci0 + ci_) * NPIX + pxl];
#pragma unroll
        for (int o = 0; o < 45; ++o) acc[o] = fmaf(yv, wsm[ci_][o], acc[o]);
    }
    if (px < NPIX) {
        float* dst = g_hp + ((long long)blockIdx.y * NPIX + px) * 45;
#pragma unroll
        for (int o = 0; o < 45; ++o) dst[o] = acc[o];
    }
}

// ---------------- 4b. heads reduce + bias + sigmoid ----------------
__global__ void heads_reduce(const float* __restrict__ bcls,
                             const float* __restrict__ bbox,
                             float* __restrict__ out) {
    int t = blockIdx.x * blockDim.x + threadIdx.x;
    if (t >= NPIX * 45) return;
    int px = t / 45, o = t - px * 45;
    float s = 0.f;
#pragma unroll
    for (int p = 0; p < 8; ++p) s += g_hp[((long long)p * NPIX + px) * 45 + o];
    if (o < 9) {
        float logit = s + bcls[o];
        out[px * 9 + o] = 1.f / (1.f + expf(-logit));
    } else {
        out[NANCH + px * 36 + (o - 9)] = s + bbox[o - 9];
    }
}

// ---------------- 5. top-k selection ----------------
__global__ void clear_kernel() {
    int t = blockIdx.x * blockDim.x + threadIdx.x;
    if (t < 65536) g_hist[t] = 0;
    if (t == 0) g_cnt = 0;
}
__global__ void hist_kernel(const float* __restrict__ out) {
    int t = blockIdx.x * blockDim.x + threadIdx.x;
    if (t >= NANCH) return;
    unsigned u = f2sortable(out[t]);
    atomicAdd(&g_hist[u >> 16], 1u);
}
__global__ void thresh_kernel() {
    __shared__ unsigned suf[257];
    int t = threadIdx.x;
    unsigned s = 0;
    for (int b = 0; b < 256; ++b) s += g_hist[t * 256 + b];
    suf[t] = s;
    __syncthreads();
    if (t == 0) {
        unsigned acc = 0;
        for (int q = 255; q >= 0; --q) { unsigned v = suf[q]; suf[q] = acc; acc += v; }
        suf[256] = acc;
    }
    __syncthreads();
    unsigned after = suf[t];
    if (after < PRE && after + s >= PRE) {
        unsigned acc = after;
        int bthr = t * 256;
        for (int b = t * 256 + 255; b >= t * 256; --b) {
            acc += g_hist[b];
            if (acc >= PRE) { bthr = b; break; }
        }
        g_bthr = (unsigned)bthr;
    }
}
__global__ void compact_kernel(const float* __restrict__ out) {
    int t = blockIdx.x * blockDim.x + threadIdx.x;
    if (t >= NANCH) return;
    unsigned u = f2sortable(out[t]);
    if ((u >> 16) >= g_bthr) {
        unsigned p = atomicAdd(&g_cnt, 1u);
        if (p < CAND_CAP)
            g_cand[p] = ((unsigned long long)u << 32) | (unsigned)t;
    }
}
__global__ void sort_kernel() {
    extern __shared__ unsigned long long sk[];
    const int tid = threadIdx.x;
    int nc = g_cnt; if (nc > CAND_CAP) nc = CAND_CAP;
    for (int i = tid; i < CAND_CAP; i += blockDim.x)
        sk[i] = (i < nc) ? g_cand[i] : 0ull;
    __syncthreads();
    for (int k = 2; k <= CAND_CAP; k <<= 1) {
        for (int j = k >> 1; j > 0; j >>= 1) {
            for (int i = tid; i < CAND_CAP; i += blockDim.x) {
                int ixj = i ^ j;
                if (ixj > i) {
                    unsigned long long a = sk[i], b = sk[ixj];
                    bool sw = ((i & k) == 0) ? (a < b) : (a > b);
                    if (sw) { sk[i] = b; sk[ixj] = a; }
                }
            }
            __syncthreads();
        }
    }
    for (int i = tid; i < PRE; i += blockDim.x) g_sorted[i] = sk[i];
}

// ---------------- 6. decode proposals ----------------
__global__ void decode_kernel(const float* __restrict__ am,
                              const int* __restrict__ ish,
                              const float* __restrict__ out) {
    int i = blockIdx.x * blockDim.x + threadIdx.x;
    if (i >= PRE) return;
    unsigned idx = (unsigned)(g_sorted[i] & 0xFFFFFFFFull);
    float a0 = am[idx * 4 + 0], a1 = am[idx * 4 + 1];
    float a2 = am[idx * 4 + 2], a3 = am[idx * 4 + 3];
    const float* d = out + NANCH + idx * 4;
    float cy = a0 + d[0] * a2;
    float cx = a1 + d[1] * a3;
    float sh = a2 * expf(d[2]);
    float sw = a3 * expf(d[3]);
    float y1 = cy - 0.5f * sh, x1 = cx - 0.5f * sw;
    float y2 = cy + 0.5f * sh, x2 = cx + 0.5f * sw;
    y1 = fmaxf(y1, 0.f); x1 = fmaxf(x1, 0.f);
    y2 = fminf(y2, (float)ish[1]);
    x2 = fminf(x2, (float)ish[2]);
    g_prop[i * 4 + 0] = y1; g_prop[i * 4 + 1] = x1;
    g_prop[i * 4 + 2] = y2; g_prop[i * 4 + 3] = x2;
    g_valid[i] = ((y2 - y1) >= 16.f) && ((x2 - x1) >= 16.f);
}

// ---------------- 7. NMS suppression bitmatrix ----------------
__global__ void nmsmat_kernel() {
    int t = blockIdx.x * blockDim.x + threadIdx.x;
    if (t >= PRE * NW) return;
    int i = t / NW;
    int w = t - i * NW;
    float y1 = g_prop[i * 4 + 0], x1 = g_prop[i * 4 + 1];
    float y2 = g_prop[i * 4 + 2], x2 = g_prop[i * 4 + 3];
    float ai = (y2 - y1) * (x2 - x1);
    unsigned bits = 0;
    int j0 = w * 32;
#pragma unroll 4
    for (int b = 0; b < 32; ++b) {
        int j = j0 + b;
        if (j < PRE && j > i) {
            float jy1 = g_prop[j * 4 + 0], jx1 = g_prop[j * 4 + 1];
            float jy2 = g_prop[j * 4 + 2], jx2 = g_prop[j * 4 + 3];
            float aj = (jy2 - jy1) * (jx2 - jx1);
            float iy1 = fmaxf(y1, jy1), ix1 = fmaxf(x1, jx1);
            float iy2 = fminf(y2, jy2), ix2 = fminf(x2, jx2);
            float inter = fmaxf(iy2 - iy1, 0.f) * fmaxf(ix2 - ix1, 0.f);
            float iou = inter / (ai + aj - inter + 1e-8f);
            if (iou > 0.7f) bits |= (1u << b);
        }
    }
    g_supp[t] = bits;
}

// ---------------- 8. sequential NMS scan (D-prefetch pipeline, proven R5) ----------------
__global__ void nmsscan_kernel() {
    __shared__ unsigned km[NW];
    const int t = threadIdx.x;  // 192
    if (t < NW) {
        unsigned bits = 0;
        for (int b = 0; b < 32; ++b) {
            int i = t * 32 + b;
            if (i < PRE && g_valid[i]) bits |= (1u << b);
        }
        km[t] = bits;
    }
    __syncthreads();
    const int D = 6;
    unsigned pre[D];
#pragma unroll
    for (int d = 0; d < D; ++d)
        pre[d] = (t < NW && d < PRE) ? g_supp[d * NW + t] : 0u;
    for (int i = 0; i < PRE; ++i) {
        unsigned row = pre[0];
#pragma unroll
        for (int d = 0; d < D - 1; ++d) pre[d] = pre[d + 1];
        int nx = i + D;
        pre[D - 1] = (t < NW && nx < PRE) ? g_supp[nx * NW + t] : 0u;
        bool kept = (km[i >> 5] >> (i & 31)) & 1u;
        if (kept && t < NW) km[t] &= ~row;
        __syncthreads();
    }
    if (t < NW) g_keep[t] = km[t];
}

// ---------------- 9. gather top-300 kept ----------------
__global__ void gather_kernel(float* __restrict__ out) {
    __shared__ unsigned pref[NW + 1];
    __shared__ unsigned kmw[NW];
    const int t = threadIdx.x;  // 256
    for (int w = t; w < NW; w += blockDim.x) kmw[w] = g_keep[w];
    __syncthreads();
    if (t == 0) {
        unsigned acc = 0;
        for (int w = 0; w < NW; ++w) { pref[w] = acc; acc += __popc(kmw[w]); }
        pref[NW] = acc;
    }
    __syncthreads();
    unsigned total = pref[NW];
    for (int i = t; i < PRE; i += blockDim.x) {
        unsigned word = kmw[i >> 5];
        if ((word >> (i & 31)) & 1u) {
            unsigned r = pref[i >> 5] + __popc(word & ((1u << (i & 31)) - 1u));
            if (r < POST) {
                out[NANCH * 5 + r * 4 + 0] = g_prop[i * 4 + 0];
                out[NANCH * 5 + r * 4 + 1] = g_prop[i * 4 + 1];
                out[NANCH * 5 + r * 4 + 2] = g_prop[i * 4 + 2];
                out[NANCH * 5 + r * 4 + 3] = g_prop[i * 4 + 3];
            }
        }
    }
    for (int k = t; k < POST; k += blockDim.x) {
        if ((unsigned)k >= total) {
            out[NANCH * 5 + k * 4 + 0] = 0.f;
            out[NANCH * 5 + k * 4 + 1] = 0.f;
            out[NANCH * 5 + k * 4 + 2] = 0.f;
            out[NANCH * 5 + k * 4 + 3] = 0.f;
        }
    }
}

// ---------------- launch ----------------
extern "C" void kernel_launch(void* const* d_in, const int* in_sizes, int n_in,
                              void* d_out, int out_size) {
    const float *feat = nullptr, *am = nullptr, *w1 = nullptr, *b1 = nullptr;
    const float *wcls = nullptr, *bcls = nullptr, *wbox = nullptr, *bbox = nullptr;
    const int *ish = nullptr;
    for (int i = 0; i < n_in; ++i) {
        switch (in_sizes[i]) {
            case 10240000: feat = (const float*)d_in[i]; break;
            case 3:        ish  = (const int*)d_in[i]; break;
            case 360000:   am   = (const float*)d_in[i]; break;
            case 9437184:  w1   = (const float*)d_in[i]; break;
            case 1024:     b1   = (const float*)d_in[i]; break;
            case 9216:     wcls = (const float*)d_in[i]; break;
            case 9:        bcls = (const float*)d_in[i]; break;
            case 36864:    wbox = (const float*)d_in[i]; break;
            case 36:       bbox = (const float*)d_in[i]; break;
            default: break;
        }
    }
    float* out = (float*)d_out;

    const int CONV_SMEM = 3 * (ASZ + BSZ);   // 153600
    cudaFuncSetAttribute(conv_mma, cudaFuncAttributeMaxDynamicSharedMemorySize, CONV_SMEM);
    cudaFuncSetAttribute(sort_kernel, cudaFuncAttributeMaxDynamicSharedMemorySize,
                         CAND_CAP * (int)sizeof(unsigned long long));

    pad_fill<<<404, 256>>>();
    {
        dim3 grid((NPIX + 31) / 32, C_IN / 32);
        dim3 blk(32, 8);
        expand_x<<<grid, blk>>>(feat);
    }
    expand_w<<<1024, 256>>>(w1);
    {
        dim3 grid(MT, 4);
        conv_mma<<<grid, 384, CONV_SMEM>>>(b1);
    }
    {
        dim3 grid((NPIX + 127) / 128, 8);
        heads_part<<<grid, 128>>>(wcls, wbox);
    }
    heads_reduce<<<(NPIX * 45 + 255) / 256, 256>>>(bcls, bbox, out);
    clear_kernel<<<65536 / 256, 256>>>();
    hist_kernel<<<(NANCH + 255) / 256, 256>>>(out);
    thresh_kernel<<<1, 256>>>();
    compact_kernel<<<(NANCH + 255) / 256, 256>>>(out);
    sort_kernel<<<1, 1024, CAND_CAP * sizeof(unsigned long long)>>>();
    decode_kernel<<<(PRE + 255) / 256, 256>>>(am, ish, out);
    nmsmat_kernel<<<(PRE * NW + 255) / 256, 256>>>();
    nmsscan_kernel<<<1, 192>>>();
    gather_kernel<<<1, 256>>>(out);
}